// round 10
// baseline (speedup 1.0000x reference)
#include <cuda_runtime.h>
#include <cstddef>
#include <cstdint>

#define BATCH   16
#define CIN     256
#define NPIX    1024
#define HEADS   8
#define DH      64
#define INNER   512
#define MQKV    1536
#define OUT_ELEMS   (BATCH * CIN * NPIX)            // 4194304

// Scratch (device globals: allocation-free rule)
__device__ float g_qkv [(size_t)BATCH * MQKV  * NPIX];   // [b][1536][1024] q|k|v (fp32)
__device__ float g_xT  [(size_t)BATCH * NPIX  * CIN ];   // [b][p][c]   tf32-rounded
__device__ float g_ctxT[(size_t)BATCH * NPIX  * INNER];  // [b][p][hd]  tf32-rounded
__device__ float g_w   [(size_t)MQKV * CIN ];            // [1536][256] tf32-rounded (Wq|Wkv)
__device__ float g_woR [(size_t)CIN  * INNER];           // [256][512]  tf32-rounded

__device__ __forceinline__ float f2tf32f(float f) {
    uint32_t u;
    asm("cvt.rna.tf32.f32 %0, %1;" : "=r"(u) : "f"(f));
    return __uint_as_float(u);
}

// ---------------------------------------------------------------------------
// Prep 1: transpose + tf32-round x: [b][c][p] -> g_xT[b][p][c]
// ---------------------------------------------------------------------------
__global__ void __launch_bounds__(256)
prep_x(const float* __restrict__ x)
{
    __shared__ float sm[32][33];
    const int b = blockIdx.z, ct = blockIdx.y, pt = blockIdx.x;
    const int t = threadIdx.x;
    const float* xb = x + ((size_t)b * CIN + ct * 32) * NPIX + pt * 32;
    const int cl = t >> 5, pl = t & 31;
    #pragma unroll
    for (int i = 0; i < 4; i++)
        sm[cl + i * 8][pl] = xb[(size_t)(cl + i * 8) * NPIX + pl];
    __syncthreads();
    float* xo = g_xT + ((size_t)b * NPIX + pt * 32) * CIN + ct * 32;
    const int pr = t >> 5, cc = t & 31;
    #pragma unroll
    for (int i = 0; i < 4; i++)
        xo[(size_t)(pr + i * 8) * CIN + cc] = f2tf32f(sm[cc][pr + i * 8]);
}

// ---------------------------------------------------------------------------
// Prep 2: round weights into g_w (Wq|Wkv) and g_woR. float4 grid-stride.
// ---------------------------------------------------------------------------
__global__ void __launch_bounds__(256)
prep_w(const float* __restrict__ Wq, const float* __restrict__ Wkv,
       const float* __restrict__ Wo)
{
    const int i = blockIdx.x * 256 + threadIdx.x;   // float4 index, grid covers 131072
    float4 v; float* dst;
    if (i < 32768)            { v = ((const float4*)Wq)[i];           dst = g_w   + (size_t)i * 4; }
    else if (i < 98304)       { v = ((const float4*)Wkv)[i - 32768];  dst = g_w   + (size_t)i * 4; }
    else                      { v = ((const float4*)Wo)[i - 98304];   dst = g_woR + (size_t)(i - 98304) * 4; }
    float4 r;
    r.x = f2tf32f(v.x); r.y = f2tf32f(v.y); r.z = f2tf32f(v.z); r.w = f2tf32f(v.w);
    *(float4*)dst = r;
}

// ---------------------------------------------------------------------------
// Pipelined TF32 tensor-core GEMM, templated on BN tile.
// C[z][m][p] = sum_k A[m][k]*B[z][p][k] (+bias)
// ---------------------------------------------------------------------------
#define BM 128
#define BK 32
#define RSW 36
#define ATILE_B (128 * RSW * 4)      // 18432 bytes

__device__ __forceinline__ void cp16(uint32_t dst, const void* src) {
    asm volatile("cp.async.cg.shared.global [%0], [%1], 16;" :: "r"(dst), "l"(src));
}
__device__ __forceinline__ void cp_commit() {
    asm volatile("cp.async.commit_group;" ::: "memory");
}
__device__ __forceinline__ void cp_wait1() {
    asm volatile("cp.async.wait_group 1;" ::: "memory");
}
__device__ __forceinline__ void ldm_x4(uint32_t r[4], uint32_t saddr) {
    asm volatile("ldmatrix.sync.aligned.m8n8.x4.shared.b16 {%0,%1,%2,%3}, [%4];"
        : "=r"(r[0]), "=r"(r[1]), "=r"(r[2]), "=r"(r[3]) : "r"(saddr));
}
__device__ __forceinline__ void mma_tf32(float c[4], const uint32_t a[4], const uint32_t b[2]) {
    asm volatile(
        "mma.sync.aligned.m16n8k8.row.col.f32.tf32.tf32.f32 "
        "{%0,%1,%2,%3},{%4,%5,%6,%7},{%8,%9},{%0,%1,%2,%3};"
        : "+f"(c[0]), "+f"(c[1]), "+f"(c[2]), "+f"(c[3])
        : "r"(a[0]), "r"(a[1]), "r"(a[2]), "r"(a[3]), "r"(b[0]), "r"(b[1]));
}

extern __shared__ uint8_t g_dsmem[];

template<int BNt>
__global__ void __launch_bounds__(256, 2)
gemm_pipe(int a_sel, int b_sel, float* __restrict__ Cext, int c_sel,
          const float* __restrict__ bias, int M, int K)
{
    constexpr int WN   = BNt / 2;
    constexpr int NJ   = WN / 8;
    constexpr int BIT  = BNt / 32;
    constexpr int BTILE_B = BNt * RSW * 4;
    constexpr int STAGE_Bc = ATILE_B + BTILE_B;

    const int n0 = blockIdx.x * BNt;
    const int m0 = blockIdx.y * BM;
    const int z  = blockIdx.z;

    const float* __restrict__ A  = (a_sel == 1) ? g_w : g_woR;
    const float* __restrict__ Bm = (b_sel == 1) ? g_xT : g_ctxT;
    float* __restrict__ C        = (c_sel == 1) ? g_qkv : Cext;

    const float* __restrict__ Ab = A + (size_t)m0 * K;
    const float* __restrict__ Bb = Bm + ((size_t)z * NPIX + n0) * K;
    C += (size_t)z * M * NPIX + (size_t)m0 * NPIX + n0;

    const uint32_t sbase = (uint32_t)__cvta_generic_to_shared(g_dsmem);

    const int tid  = threadIdx.x;
    const int lane = tid & 31;
    const int warp = tid >> 5;
    const int wm0  = (warp >> 1) * 32;
    const int wn0  = (warp & 1) * WN;
    const int grp  = lane >> 2;
    const int qid  = lane & 3;

    const int sr  = tid >> 3;
    const int seg = tid & 7;

    const int a_mrow = ((lane >> 3) & 1) * 8 + (lane & 7);
    const int a_koff = ((lane >> 4) & 1) * 4;
    const int b_nrow = ((lane >> 4) & 1) * 8 + (lane & 7);
    const int b_koff = ((lane >> 3) & 1) * 4;

    float acc[2][NJ][4];
    #pragma unroll
    for (int mt = 0; mt < 2; mt++)
        #pragma unroll
        for (int j = 0; j < NJ; j++)
            #pragma unroll
            for (int e = 0; e < 4; e++) acc[mt][j][e] = 0.f;

    const int NT = K / BK;

    auto stage = [&](int kt, int s) {
        const uint32_t aB = sbase + s * STAGE_Bc;
        const uint32_t bB = aB + ATILE_B;
        const int kw = kt * BK + seg * 4;
        #pragma unroll
        for (int it = 0; it < 4; it++) {
            int r = sr + it * 32;
            cp16(aB + r * (RSW * 4) + seg * 16, Ab + (size_t)r * K + kw);
        }
        #pragma unroll
        for (int it = 0; it < BIT; it++) {
            int r = sr + it * 32;
            cp16(bB + r * (RSW * 4) + seg * 16, Bb + (size_t)r * K + kw);
        }
    };

    stage(0, 0);
    cp_commit();

    for (int kt = 0; kt < NT; kt++) {
        if (kt + 1 < NT) stage(kt + 1, (kt + 1) & 1);
        cp_commit();
        cp_wait1();
        __syncthreads();

        const uint32_t aS = sbase + (kt & 1) * STAGE_Bc;
        const uint32_t bS = aS + ATILE_B;

        #pragma unroll
        for (int ks = 0; ks < 4; ks++) {
            uint32_t afr[2][4];
            #pragma unroll
            for (int mt = 0; mt < 2; mt++)
                ldm_x4(afr[mt], aS + (wm0 + mt * 16 + a_mrow) * (RSW * 4)
                                   + (ks * 8 + a_koff) * 4);
            uint32_t bfr[NJ][2];
            #pragma unroll
            for (int jj = 0; jj < NJ / 2; jj++) {
                uint32_t r[4];
                ldm_x4(r, bS + (wn0 + jj * 16 + b_nrow) * (RSW * 4)
                             + (ks * 8 + b_koff) * 4);
                bfr[jj * 2 + 0][0] = r[0]; bfr[jj * 2 + 0][1] = r[1];
                bfr[jj * 2 + 1][0] = r[2]; bfr[jj * 2 + 1][1] = r[3];
            }
            #pragma unroll
            for (int mt = 0; mt < 2; mt++)
                #pragma unroll
                for (int j = 0; j < NJ; j++)
                    mma_tf32(acc[mt][j], afr[mt], bfr[j]);
        }
        __syncthreads();
    }

    #pragma unroll
    for (int mt = 0; mt < 2; mt++) {
        #pragma unroll
        for (int e2 = 0; e2 < 2; e2++) {
            int mloc = wm0 + mt * 16 + grp + e2 * 8;
            float bv = bias ? bias[m0 + mloc] : 0.f;
            #pragma unroll
            for (int j = 0; j < NJ; j++) {
                float2 r;
                r.x = acc[mt][j][e2 * 2 + 0] + bv;
                r.y = acc[mt][j][e2 * 2 + 1] + bv;
                *(float2*)(C + (size_t)mloc * NPIX + wn0 + j * 8 + 2 * qid) = r;
            }
        }
    }
}

// ---------------------------------------------------------------------------
// 3x3 windowed attention — register/shuffle version. NO smem, NO barriers.
// Warp = one 32-pixel image row. Per d-plane: 3 coalesced row loads
// (y-1, y, y+1; OOB rows predicated to 0 == zero-pad) + shfl for x+-1
// (lane 0/31 shuffles zeroed == zero-pad). OOB logits therefore exactly 0.
// Emits attn [b,h,n,9] and ctx transposed + tf32-rounded g_ctxT[b][p][h*64+d].
// ---------------------------------------------------------------------------
__global__ void __launch_bounds__(256)
attn_kernel(float* __restrict__ attn_out)
{
    const int tid  = threadIdx.x;
    const int lane = tid & 31;
    const int warp = tid >> 5;
    const int y    = blockIdx.x * 8 + warp;   // image row
    const int x    = lane;                    // image col
    const int h    = blockIdx.y;
    const int b    = blockIdx.z;
    const int p    = y * 32 + x;

    const float* __restrict__ qb = g_qkv + ((size_t)b * MQKV +        h * DH) * NPIX + p;
    const float* __restrict__ kb = g_qkv + ((size_t)b * MQKV +  512 + h * DH) * NPIX + p;
    const float* __restrict__ vb = g_qkv + ((size_t)b * MQKV + 1024 + h * DH) * NPIX + p;

    const bool okm = (y > 0);
    const bool okp = (y < 31);
    const unsigned FULL = 0xffffffffu;

    float dots[9];
    #pragma unroll
    for (int w = 0; w < 9; w++) dots[w] = 0.f;

    // ---- Pass 1: dots = q . k ----
    #pragma unroll 8
    for (int d = 0; d < DH; d++) {
        const float* kp = kb + (size_t)d * NPIX;
        float qd  = qb[(size_t)d * NPIX];
        float km  = okm ? kp[-32] : 0.f;
        float kc  = kp[0];
        float kpv = okp ? kp[32]  : 0.f;
        float kml = __shfl_up_sync  (FULL, km,  1);
        float kcl = __shfl_up_sync  (FULL, kc,  1);
        float kpl = __shfl_up_sync  (FULL, kpv, 1);
        float kmr = __shfl_down_sync(FULL, km,  1);
        float kcr = __shfl_down_sync(FULL, kc,  1);
        float kpr = __shfl_down_sync(FULL, kpv, 1);
        if (lane == 0)  { kml = 0.f; kcl = 0.f; kpl = 0.f; }
        if (lane == 31) { kmr = 0.f; kcr = 0.f; kpr = 0.f; }
        dots[0] += qd * kml; dots[1] += qd * km;  dots[2] += qd * kmr;
        dots[3] += qd * kcl; dots[4] += qd * kc;  dots[5] += qd * kcr;
        dots[6] += qd * kpl; dots[7] += qd * kpv; dots[8] += qd * kpr;
    }

    // softmax over 9 (OOB logits exactly 0)
    const float scale = 0.125f;
    float mx = -1e30f;
    #pragma unroll
    for (int w = 0; w < 9; w++) { dots[w] *= scale; mx = fmaxf(mx, dots[w]); }
    float a[9], sum = 0.f;
    #pragma unroll
    for (int w = 0; w < 9; w++) { a[w] = expf(dots[w] - mx); sum += a[w]; }
    float inv = 1.f / sum;
    #pragma unroll
    for (int w = 0; w < 9; w++) a[w] *= inv;

    {
        float* ao = attn_out + ((size_t)(b * HEADS + h) * NPIX + p) * 9;
        #pragma unroll
        for (int w = 0; w < 9; w++) ao[w] = a[w];
    }

    // ---- Pass 2: ctx = attn . v (4 d's per float4 store) ----
    float* __restrict__ ct = g_ctxT + ((size_t)b * NPIX + p) * INNER + h * DH;
    #pragma unroll 2
    for (int dc = 0; dc < DH; dc += 4) {
        float acc4[4];
        #pragma unroll
        for (int dd = 0; dd < 4; dd++) {
            const float* vp = vb + (size_t)(dc + dd) * NPIX;
            float vm  = okm ? vp[-32] : 0.f;
            float vc  = vp[0];
            float vpv = okp ? vp[32]  : 0.f;
            float vml = __shfl_up_sync  (FULL, vm,  1);
            float vcl = __shfl_up_sync  (FULL, vc,  1);
            float vpl = __shfl_up_sync  (FULL, vpv, 1);
            float vmr = __shfl_down_sync(FULL, vm,  1);
            float vcr = __shfl_down_sync(FULL, vc,  1);
            float vpr = __shfl_down_sync(FULL, vpv, 1);
            if (lane == 0)  { vml = 0.f; vcl = 0.f; vpl = 0.f; }
            if (lane == 31) { vmr = 0.f; vcr = 0.f; vpr = 0.f; }
            float s = a[0] * vml + a[1] * vm  + a[2] * vmr
                    + a[3] * vcl + a[4] * vc  + a[5] * vcr
                    + a[6] * vpl + a[7] * vpv + a[8] * vpr;
            acc4[dd] = f2tf32f(s);
        }
        *(float4*)(ct + dc) = make_float4(acc4[0], acc4[1], acc4[2], acc4[3]);
    }
}

// ---------------------------------------------------------------------------
extern "C" void kernel_launch(void* const* d_in, const int* in_sizes, int n_in,
                              void* d_out, int out_size)
{
    const float* x   = (const float*)d_in[0];
    const float* Wq  = (const float*)d_in[1];
    const float* Wkv = (const float*)d_in[2];
    const float* Wo  = (const float*)d_in[3];
    const float* bo  = (const float*)d_in[4];
    float* out = (float*)d_out;     // out (4194304) | attn (1179648)

    constexpr int SMEM128 = 2 * (ATILE_B + 128 * RSW * 4);   // 73728

    static int smem_set = 0;
    if (!smem_set) {
        cudaFuncSetAttribute(gemm_pipe<128>,
                             cudaFuncAttributeMaxDynamicSharedMemorySize, SMEM128);
        smem_set = 1;
    }

    // prep: transpose+round x, round weights
    {
        dim3 g(32, 8, BATCH);
        prep_x<<<g, 256>>>(x);
        prep_w<<<512, 256>>>(Wq, Wkv, Wo);
    }

    // QKV: g_qkv[b][m][p] = g_w[m][:] . g_xT[b][p][:]
    {
        dim3 grid(NPIX / 128, MQKV / BM, BATCH);   // (8, 12, 16)
        gemm_pipe<128><<<grid, 256, SMEM128>>>(1, 1, nullptr, 1, nullptr, MQKV, CIN);
    }

    // attention -> attn tail + g_ctxT  (no smem, no barriers)
    {
        dim3 grid(4, HEADS, BATCH);                // 512 blocks
        attn_kernel<<<grid, 256>>>(out + OUT_ELEMS);
    }

    // out projection: out[b][c][p] = g_woR[c][:] . g_ctxT[b][p][:] + bo[c]
    {
        dim3 grid(NPIX / 128, CIN / BM, BATCH);    // (8, 2, 16)
        gemm_pipe<128><<<grid, 256, SMEM128>>>(2, 2, out, 0, bo, CIN, INNER);
    }
}

// round 12
// speedup vs baseline: 1.6048x; 1.6048x over previous
#include <cuda_runtime.h>
#include <cuda_fp16.h>
#include <cstddef>
#include <cstdint>

#define BATCH   16
#define CIN     256
#define NPIX    1024
#define HEADS   8
#define DH      64
#define INNER   512
#define MQKV    1536
#define OUT_ELEMS   (BATCH * CIN * NPIX)            // 4194304

// Scratch (device globals: allocation-free rule) — fp16 intermediates
__device__ __half g_qkvh[(size_t)BATCH * MQKV * NPIX];   // [b][1536][1024] q|k|v
__device__ __half g_xh  [(size_t)BATCH * NPIX * CIN ];   // [b][p][c]
__device__ __half g_ctxh[(size_t)BATCH * NPIX * INNER];  // [b][p][hd]
__device__ __half g_wh  [(size_t)MQKV * CIN ];           // [1536][256] (Wq|Wkv)
__device__ __half g_woh [(size_t)CIN  * INNER];          // [256][512]

// ---------------------------------------------------------------------------
// cp.async helpers
// ---------------------------------------------------------------------------
__device__ __forceinline__ void cp16(uint32_t dst, const void* src) {
    asm volatile("cp.async.cg.shared.global [%0], [%1], 16;" :: "r"(dst), "l"(src));
}
__device__ __forceinline__ void cp4z(uint32_t dst, const void* src, bool ok) {
    int sz = ok ? 4 : 0;
    asm volatile("cp.async.ca.shared.global [%0], [%1], 4, %2;"
                 :: "r"(dst), "l"(src), "r"(sz));
}
__device__ __forceinline__ void cp_commit() {
    asm volatile("cp.async.commit_group;" ::: "memory");
}
__device__ __forceinline__ void cp_wait1() {
    asm volatile("cp.async.wait_group 1;" ::: "memory");
}
__device__ __forceinline__ void cp_wait0() {
    asm volatile("cp.async.wait_group 0;" ::: "memory");
}
__device__ __forceinline__ void ldm_x4(uint32_t r[4], uint32_t saddr) {
    asm volatile("ldmatrix.sync.aligned.m8n8.x4.shared.b16 {%0,%1,%2,%3}, [%4];"
        : "=r"(r[0]), "=r"(r[1]), "=r"(r[2]), "=r"(r[3]) : "r"(saddr));
}
__device__ __forceinline__ void mma_f16(float c[4], const uint32_t a[4], const uint32_t b[2]) {
    asm volatile(
        "mma.sync.aligned.m16n8k16.row.col.f32.f16.f16.f32 "
        "{%0,%1,%2,%3},{%4,%5,%6,%7},{%8,%9},{%0,%1,%2,%3};"
        : "+f"(c[0]), "+f"(c[1]), "+f"(c[2]), "+f"(c[3])
        : "r"(a[0]), "r"(a[1]), "r"(a[2]), "r"(a[3]), "r"(b[0]), "r"(b[1]));
}

// ---------------------------------------------------------------------------
// Prep 1: transpose + fp16-round x: [b][c][p] -> g_xh[b][p][c]
// ---------------------------------------------------------------------------
__global__ void __launch_bounds__(256)
prep_x(const float* __restrict__ x)
{
    __shared__ float sm[32][33];
    const int b = blockIdx.z, ct = blockIdx.y, pt = blockIdx.x;
    const int t = threadIdx.x;
    const float* xb = x + ((size_t)b * CIN + ct * 32) * NPIX + pt * 32;
    const int cl = t >> 5, pl = t & 31;
    #pragma unroll
    for (int i = 0; i < 4; i++)
        sm[cl + i * 8][pl] = xb[(size_t)(cl + i * 8) * NPIX + pl];
    __syncthreads();
    __half* xo = g_xh + ((size_t)b * NPIX + pt * 32) * CIN + ct * 32;
    const int pr = t >> 5, cc = t & 31;
    #pragma unroll
    for (int i = 0; i < 4; i++)
        xo[(size_t)(pr + i * 8) * CIN + cc] = __float2half_rn(sm[cc][pr + i * 8]);
}

// ---------------------------------------------------------------------------
// Prep 2: fp16-round weights into g_wh (Wq|Wkv) and g_woh.
// ---------------------------------------------------------------------------
__global__ void __launch_bounds__(256)
prep_w(const float* __restrict__ Wq, const float* __restrict__ Wkv,
       const float* __restrict__ Wo)
{
    const int i = blockIdx.x * 256 + threadIdx.x;   // float4 index, grid covers 131072
    float4 v; __half* dst;
    if (i < 32768)      { v = ((const float4*)Wq)[i];          dst = g_wh  + (size_t)i * 4; }
    else if (i < 98304) { v = ((const float4*)Wkv)[i - 32768]; dst = g_wh  + (size_t)i * 4; }
    else                { v = ((const float4*)Wo)[i - 98304];  dst = g_woh + (size_t)(i - 98304) * 4; }
    *(half2*)(dst)     = __floats2half2_rn(v.x, v.y);
    *(half2*)(dst + 2) = __floats2half2_rn(v.z, v.w);
}

// ---------------------------------------------------------------------------
// Pipelined FP16 tensor-core GEMM (mma.m16n8k16, f32 accum).
// C[z][m][p] = sum_k A[m][k] * B[z][p][k]   A:[M][K] h, B:[z][1024][K] h.
// Tile 128x128, chunk BK=64 halves (128B rows, stride 144B — conflict-free
// ldmatrix: banks walk 4r mod 32). 2-stage cp.async double buffer.
// 8 warps (4m x 2n), warp tile 32x64. Output half (qkv) or float+bias (out).
// ---------------------------------------------------------------------------
#define BKH 64                        // halves per chunk row
#define RSB 144                       // smem row stride bytes
#define TILE_BH (128 * RSB)           // 18432 B per operand tile
#define STAGE_BH (2 * TILE_BH)        // 36864 B (A then B)
#define SMEM_GH (2 * STAGE_BH)        // 73728 B

extern __shared__ uint8_t g_dsmem[];

__global__ void __launch_bounds__(256, 2)
gemm_h(int a_sel, int b_sel, float* __restrict__ Cext, int c_sel,
       const float* __restrict__ bias, int M, int K)
{
    const int n0 = blockIdx.x * 128;
    const int m0 = blockIdx.y * 128;
    const int z  = blockIdx.z;

    const __half* __restrict__ A  = (a_sel == 1) ? g_wh : g_woh;
    const __half* __restrict__ Bm = (b_sel == 1) ? g_xh : g_ctxh;

    const __half* __restrict__ Ab = A + (size_t)m0 * K;
    const __half* __restrict__ Bb = Bm + ((size_t)z * NPIX + n0) * K;

    __half* Ch = g_qkvh + (size_t)z * MQKV * NPIX + (size_t)m0 * NPIX + n0;
    float*  Cf = Cext   + (size_t)z * CIN  * NPIX + (size_t)m0 * NPIX + n0;

    const uint32_t sbase = (uint32_t)__cvta_generic_to_shared(g_dsmem);

    const int tid  = threadIdx.x;
    const int lane = tid & 31;
    const int warp = tid >> 5;
    const int wm0  = (warp >> 1) * 32;
    const int wn0  = (warp & 1) * 64;
    const int grp  = lane >> 2;
    const int qid  = lane & 3;

    const int sr  = tid >> 3;        // staging base row (advances by 32)
    const int seg = tid & 7;         // 16B segment in 128B row

    // ldmatrix per-lane offsets (canonical m16n8k16 fragment maps)
    const int a_r = ((lane >> 3) & 1) * 8 + (lane & 7);
    const int a_k = ((lane >> 4) & 1) * 16;
    const int b_r = ((lane >> 4) & 1) * 8 + (lane & 7);
    const int b_k = ((lane >> 3) & 1) * 16;

    float acc[2][8][4];
    #pragma unroll
    for (int mt = 0; mt < 2; mt++)
        #pragma unroll
        for (int j = 0; j < 8; j++)
            #pragma unroll
            for (int e = 0; e < 4; e++) acc[mt][j][e] = 0.f;

    const int NT = K / BKH;

    auto stage = [&](int kt, int s) {
        const uint32_t aB = sbase + s * STAGE_BH;
        const uint32_t bB = aB + TILE_BH;
        const int kh = kt * BKH + seg * 8;       // halves
        #pragma unroll
        for (int it = 0; it < 4; it++) {
            int r = sr + it * 32;
            cp16(aB + r * RSB + seg * 16, Ab + (size_t)r * K + kh);
            cp16(bB + r * RSB + seg * 16, Bb + (size_t)r * K + kh);
        }
    };

    stage(0, 0);
    cp_commit();

    for (int kt = 0; kt < NT; kt++) {
        if (kt + 1 < NT) stage(kt + 1, (kt + 1) & 1);
        cp_commit();
        cp_wait1();
        __syncthreads();

        const uint32_t aS = sbase + (kt & 1) * STAGE_BH;
        const uint32_t bS = aS + TILE_BH;

        #pragma unroll
        for (int s = 0; s < 4; s++) {            // 4 x k16 steps
            const int kb = s * 32;               // byte offset in row
            uint32_t afr[2][4];
            #pragma unroll
            for (int mt = 0; mt < 2; mt++)
                ldm_x4(afr[mt], aS + (wm0 + mt * 16 + a_r) * RSB + kb + a_k);
            uint32_t bfr[8][2];
            #pragma unroll
            for (int jj = 0; jj < 4; jj++) {
                uint32_t r[4];
                ldm_x4(r, bS + (wn0 + jj * 16 + b_r) * RSB + kb + b_k);
                bfr[jj * 2 + 0][0] = r[0]; bfr[jj * 2 + 0][1] = r[1];
                bfr[jj * 2 + 1][0] = r[2]; bfr[jj * 2 + 1][1] = r[3];
            }
            #pragma unroll
            for (int mt = 0; mt < 2; mt++)
                #pragma unroll
                for (int j = 0; j < 8; j++)
                    mma_f16(acc[mt][j], afr[mt], bfr[j]);
        }
        __syncthreads();
    }

    // Epilogue
    #pragma unroll
    for (int mt = 0; mt < 2; mt++) {
        #pragma unroll
        for (int e2 = 0; e2 < 2; e2++) {
            int mloc = wm0 + mt * 16 + grp + e2 * 8;
            if (c_sel == 1) {
                #pragma unroll
                for (int j = 0; j < 8; j++) {
                    half2 hv = __floats2half2_rn(acc[mt][j][e2 * 2 + 0],
                                                 acc[mt][j][e2 * 2 + 1]);
                    *(half2*)(Ch + (size_t)mloc * NPIX + wn0 + j * 8 + 2 * qid) = hv;
                }
            } else {
                float bv = bias[m0 + mloc];
                #pragma unroll
                for (int j = 0; j < 8; j++) {
                    float2 r;
                    r.x = acc[mt][j][e2 * 2 + 0] + bv;
                    r.y = acc[mt][j][e2 * 2 + 1] + bv;
                    *(float2*)(Cf + (size_t)mloc * NPIX + wn0 + j * 8 + 2 * qid) = r;
                }
            }
        }
    }
}

// ---------------------------------------------------------------------------
// 3x3 windowed attention (fp16 tiles, R7 pipeline structure).
// Block = 8row x 32col slab of one (b,h). Warp w stages d-plane (dc+w).
// Tile row layout (36 halves): col j = gx + 2 for gx in [0,32); j=1 and j=34
// are the x-halo — ALWAYS zero for a 32-wide image, pre-zeroed once.
// Interior staged as aligned 4B half-pairs with cp.async zfill (row-OOB -> 0).
// Zero-pad semantics: OOB logit contribution exactly 0.
// ---------------------------------------------------------------------------
#define DCH 8
#define TRR 10
#define TCH 36
#define PLANE_B (TRR * TCH * 2)          // 720 bytes per d-plane
#define TBUF_B (DCH * PLANE_B)           // 5760 bytes per buffer

__global__ void __launch_bounds__(256)
attn_kernel(float* __restrict__ attn_out)
{
    __shared__ __half tile[2][DCH][TRR][TCH];   // 11.5 KB double-buffered

    const int tid  = threadIdx.x;
    const int lane = tid & 31;
    const int warp = tid >> 5;
    const int ry   = warp;
    const int x    = lane;
    const int r0   = blockIdx.x * 8;
    const int h    = blockIdx.y;
    const int b    = blockIdx.z;
    const int p    = (r0 + ry) * 32 + x;

    const __half* __restrict__ qb = g_qkvh + ((size_t)b * MQKV +        h * DH) * NPIX;
    const __half* __restrict__ kb = g_qkvh + ((size_t)b * MQKV +  512 + h * DH) * NPIX;
    const __half* __restrict__ vb = g_qkvh + ((size_t)b * MQKV + 1024 + h * DH) * NPIX;

    const uint32_t tb = (uint32_t)__cvta_generic_to_shared(&tile[0][0][0][0]);

    // Pre-zero the always-zero x-halo columns (j=1, j=34) for both buffers.
    for (int idx = tid; idx < 2 * DCH * TRR; idx += 256) {
        int buf = idx / (DCH * TRR);
        int rem = idx - buf * (DCH * TRR);
        int d = rem / TRR, rr = rem - d * TRR;
        tile[buf][d][rr][1]  = __float2half(0.f);
        tile[buf][d][rr][34] = __float2half(0.f);
    }

    // warp stages plane (dc + warp) into buffer s: 10 rows x 16 pairs
    auto stage = [&](const __half* __restrict__ src_base, int dc, int s) {
        const __half* __restrict__ src = src_base + (size_t)(dc + warp) * NPIX;
        const uint32_t dst = tb + (uint32_t)(s * TBUF_B + warp * PLANE_B);
        #pragma unroll
        for (int i0 = 0; i0 < 5; i0++) {
            const int i  = lane + i0 * 32;      // 0..159
            const int rr = i >> 4;
            const int t  = i & 15;              // pair: gx = 2t,2t+1 -> j = 2t+2
            const int gy = r0 + rr - 1;
            cp4z(dst + (uint32_t)(rr * (TCH * 2) + (2 * t + 2) * 2),
                 src + gy * 32 + 2 * t, ((unsigned)gy < 32u));
        }
    };

    float dots[9];
    #pragma unroll
    for (int w = 0; w < 9; w++) dots[w] = 0.f;

    stage(kb, 0, 0); cp_commit();
    stage(kb, DCH, 1); cp_commit();

    #pragma unroll 1
    for (int c = 0; c < DH / DCH; c++) {
        if (c == DH / DCH - 1) cp_wait0(); else cp_wait1();
        __syncthreads();
        const int s = c & 1;
        const int dc = c * DCH;
        #pragma unroll
        for (int dd = 0; dd < DCH; dd++) {
            float qd = __half2float(qb[(size_t)(dc + dd) * NPIX + p]);
            #pragma unroll
            for (int w = 0; w < 9; w++)
                dots[w] += qd * __half2float(tile[s][dd][ry + w / 3][x + 1 + w % 3]);
        }
        __syncthreads();
        if (c + 2 < DH / DCH) { stage(kb, (c + 2) * DCH, s); cp_commit(); }
    }

    // softmax over 9 (OOB logits exactly 0)
    const float scale = 0.125f;
    float mx = -1e30f;
    #pragma unroll
    for (int w = 0; w < 9; w++) { dots[w] *= scale; mx = fmaxf(mx, dots[w]); }
    float a[9], sum = 0.f;
    #pragma unroll
    for (int w = 0; w < 9; w++) { a[w] = expf(dots[w] - mx); sum += a[w]; }
    float inv = 1.f / sum;
    #pragma unroll
    for (int w = 0; w < 9; w++) a[w] *= inv;

    {
        float* ao = attn_out + ((size_t)(b * HEADS + h) * NPIX + p) * 9;
        #pragma unroll
        for (int w = 0; w < 9; w++) ao[w] = a[w];
    }

    // Pass 2: ctx = attn . v -> g_ctxh[b][p][h*64+d]
    __half* __restrict__ ct = g_ctxh + ((size_t)b * NPIX + p) * INNER + h * DH;

    stage(vb, 0, 0); cp_commit();
    stage(vb, DCH, 1); cp_commit();

    #pragma unroll 1
    for (int c = 0; c < DH / DCH; c++) {
        if (c == DH / DCH - 1) cp_wait0(); else cp_wait1();
        __syncthreads();
        const int s = c & 1;
        const int dc = c * DCH;
        float acc8[DCH];
        #pragma unroll
        for (int dd = 0; dd < DCH; dd++) {
            float sacc = 0.f;
            #pragma unroll
            for (int w = 0; w < 9; w++)
                sacc += a[w] * __half2float(tile[s][dd][ry + w / 3][x + 1 + w % 3]);
            acc8[dd] = sacc;
        }
        #pragma unroll
        for (int i = 0; i < 4; i++)
            *(half2*)(ct + dc + 2 * i) = __floats2half2_rn(acc8[2 * i], acc8[2 * i + 1]);
        __syncthreads();
        if (c + 2 < DH / DCH) { stage(vb, (c + 2) * DCH, s); cp_commit(); }
    }
}

// ---------------------------------------------------------------------------
extern "C" void kernel_launch(void* const* d_in, const int* in_sizes, int n_in,
                              void* d_out, int out_size)
{
    const float* x   = (const float*)d_in[0];
    const float* Wq  = (const float*)d_in[1];
    const float* Wkv = (const float*)d_in[2];
    const float* Wo  = (const float*)d_in[3];
    const float* bo  = (const float*)d_in[4];
    float* out = (float*)d_out;     // out (4194304) | attn (1179648)

    static int smem_set = 0;
    if (!smem_set) {
        cudaFuncSetAttribute(gemm_h, cudaFuncAttributeMaxDynamicSharedMemorySize,
                             SMEM_GH);
        smem_set = 1;
    }

    // prep: transpose+round x, round weights (fp16)
    {
        dim3 g(32, 8, BATCH);
        prep_x<<<g, 256>>>(x);
        prep_w<<<512, 256>>>(Wq, Wkv, Wo);
    }

    // QKV: g_qkvh[b][m][p] = g_wh[m][:] . g_xh[b][p][:]   (K=256, NT=4)
    {
        dim3 grid(NPIX / 128, MQKV / 128, BATCH);   // (8, 12, 16)
        gemm_h<<<grid, 256, SMEM_GH>>>(1, 1, nullptr, 1, nullptr, MQKV, CIN);
    }

    // attention -> attn tail + g_ctxh
    {
        dim3 grid(4, HEADS, BATCH);
        attn_kernel<<<grid, 256>>>(out + OUT_ELEMS);
    }

    // out projection: out[b][c][p] = g_woh[c][:] . g_ctxh[b][p][:] + bo[c]  (K=512, NT=8)
    {
        dim3 grid(NPIX / 128, CIN / 128, BATCH);    // (8, 2, 16)
        gemm_h<<<grid, 256, SMEM_GH>>>(2, 2, out, 0, bo, CIN, INNER);
    }
}

// round 13
// speedup vs baseline: 1.7239x; 1.0742x over previous
#include <cuda_runtime.h>
#include <cuda_fp16.h>
#include <cstddef>
#include <cstdint>

#define BATCH   16
#define CIN     256
#define NPIX    1024
#define HEADS   8
#define DH      64
#define INNER   512
#define MQKV    1536
#define OUT_ELEMS   (BATCH * CIN * NPIX)            // 4194304

// Scratch (device globals: allocation-free rule) — fp16 intermediates
__device__ __half g_qkvh[(size_t)BATCH * MQKV * NPIX];   // [b][1536][1024] q|k|v
__device__ __half g_xh  [(size_t)BATCH * NPIX * CIN ];   // [b][p][c]
__device__ __half g_ctxh[(size_t)BATCH * NPIX * INNER];  // [b][p][hd]
__device__ __half g_wh  [(size_t)MQKV * CIN ];           // [1536][256] (Wq|Wkv)
__device__ __half g_woh [(size_t)CIN  * INNER];          // [256][512]

// ---------------------------------------------------------------------------
// cp.async helpers
// ---------------------------------------------------------------------------
__device__ __forceinline__ void cp16(uint32_t dst, const void* src) {
    asm volatile("cp.async.cg.shared.global [%0], [%1], 16;" :: "r"(dst), "l"(src));
}
__device__ __forceinline__ void cp4z(uint32_t dst, const void* src, bool ok) {
    int sz = ok ? 4 : 0;
    asm volatile("cp.async.ca.shared.global [%0], [%1], 4, %2;"
                 :: "r"(dst), "l"(src), "r"(sz));
}
__device__ __forceinline__ void cp_commit() {
    asm volatile("cp.async.commit_group;" ::: "memory");
}
__device__ __forceinline__ void cp_wait1() {
    asm volatile("cp.async.wait_group 1;" ::: "memory");
}
__device__ __forceinline__ void cp_wait2() {
    asm volatile("cp.async.wait_group 2;" ::: "memory");
}
__device__ __forceinline__ void ldm_x4(uint32_t r[4], uint32_t saddr) {
    asm volatile("ldmatrix.sync.aligned.m8n8.x4.shared.b16 {%0,%1,%2,%3}, [%4];"
        : "=r"(r[0]), "=r"(r[1]), "=r"(r[2]), "=r"(r[3]) : "r"(saddr));
}
__device__ __forceinline__ void mma_f16(float c[4], const uint32_t a[4], const uint32_t b[2]) {
    asm volatile(
        "mma.sync.aligned.m16n8k16.row.col.f32.f16.f16.f32 "
        "{%0,%1,%2,%3},{%4,%5,%6,%7},{%8,%9},{%0,%1,%2,%3};"
        : "+f"(c[0]), "+f"(c[1]), "+f"(c[2]), "+f"(c[3])
        : "r"(a[0]), "r"(a[1]), "r"(a[2]), "r"(a[3]), "r"(b[0]), "r"(b[1]));
}

// ---------------------------------------------------------------------------
// Prep 1: transpose + fp16-round x: [b][c][p] -> g_xh[b][p][c]
// ---------------------------------------------------------------------------
__global__ void __launch_bounds__(256)
prep_x(const float* __restrict__ x)
{
    __shared__ float sm[32][33];
    const int b = blockIdx.z, ct = blockIdx.y, pt = blockIdx.x;
    const int t = threadIdx.x;
    const float* xb = x + ((size_t)b * CIN + ct * 32) * NPIX + pt * 32;
    const int cl = t >> 5, pl = t & 31;
    #pragma unroll
    for (int i = 0; i < 4; i++)
        sm[cl + i * 8][pl] = xb[(size_t)(cl + i * 8) * NPIX + pl];
    __syncthreads();
    __half* xo = g_xh + ((size_t)b * NPIX + pt * 32) * CIN + ct * 32;
    const int pr = t >> 5, cc = t & 31;
    #pragma unroll
    for (int i = 0; i < 4; i++)
        xo[(size_t)(pr + i * 8) * CIN + cc] = __float2half_rn(sm[cc][pr + i * 8]);
}

// ---------------------------------------------------------------------------
// Prep 2: fp16-round weights into g_wh (Wq|Wkv) and g_woh.
// ---------------------------------------------------------------------------
__global__ void __launch_bounds__(256)
prep_w(const float* __restrict__ Wq, const float* __restrict__ Wkv,
       const float* __restrict__ Wo)
{
    const int i = blockIdx.x * 256 + threadIdx.x;   // float4 index, grid covers 131072
    float4 v; __half* dst;
    if (i < 32768)      { v = ((const float4*)Wq)[i];          dst = g_wh  + (size_t)i * 4; }
    else if (i < 98304) { v = ((const float4*)Wkv)[i - 32768]; dst = g_wh  + (size_t)i * 4; }
    else                { v = ((const float4*)Wo)[i - 98304];  dst = g_woh + (size_t)(i - 98304) * 4; }
    *(half2*)(dst)     = __floats2half2_rn(v.x, v.y);
    *(half2*)(dst + 2) = __floats2half2_rn(v.z, v.w);
}

// ---------------------------------------------------------------------------
// Pipelined FP16 tensor-core GEMM (mma.m16n8k16, f32 accum) — unchanged R11.
// ---------------------------------------------------------------------------
#define BKH 64
#define RSB 144
#define TILE_BH (128 * RSB)
#define STAGE_BH (2 * TILE_BH)
#define SMEM_GH (2 * STAGE_BH)       // 73728 B

extern __shared__ uint8_t g_dsmem[];

__global__ void __launch_bounds__(256, 2)
gemm_h(int a_sel, int b_sel, float* __restrict__ Cext, int c_sel,
       const float* __restrict__ bias, int M, int K)
{
    const int n0 = blockIdx.x * 128;
    const int m0 = blockIdx.y * 128;
    const int z  = blockIdx.z;

    const __half* __restrict__ A  = (a_sel == 1) ? g_wh : g_woh;
    const __half* __restrict__ Bm = (b_sel == 1) ? g_xh : g_ctxh;

    const __half* __restrict__ Ab = A + (size_t)m0 * K;
    const __half* __restrict__ Bb = Bm + ((size_t)z * NPIX + n0) * K;

    __half* Ch = g_qkvh + (size_t)z * MQKV * NPIX + (size_t)m0 * NPIX + n0;
    float*  Cf = Cext   + (size_t)z * CIN  * NPIX + (size_t)m0 * NPIX + n0;

    const uint32_t sbase = (uint32_t)__cvta_generic_to_shared(g_dsmem);

    const int tid  = threadIdx.x;
    const int lane = tid & 31;
    const int warp = tid >> 5;
    const int wm0  = (warp >> 1) * 32;
    const int wn0  = (warp & 1) * 64;
    const int grp  = lane >> 2;
    const int qid  = lane & 3;

    const int sr  = tid >> 3;
    const int seg = tid & 7;

    const int a_r = ((lane >> 3) & 1) * 8 + (lane & 7);
    const int a_k = ((lane >> 4) & 1) * 16;
    const int b_r = ((lane >> 4) & 1) * 8 + (lane & 7);
    const int b_k = ((lane >> 3) & 1) * 16;

    float acc[2][8][4];
    #pragma unroll
    for (int mt = 0; mt < 2; mt++)
        #pragma unroll
        for (int j = 0; j < 8; j++)
            #pragma unroll
            for (int e = 0; e < 4; e++) acc[mt][j][e] = 0.f;

    const int NT = K / BKH;

    auto stage = [&](int kt, int s) {
        const uint32_t aB = sbase + s * STAGE_BH;
        const uint32_t bB = aB + TILE_BH;
        const int kh = kt * BKH + seg * 8;
        #pragma unroll
        for (int it = 0; it < 4; it++) {
            int r = sr + it * 32;
            cp16(aB + r * RSB + seg * 16, Ab + (size_t)r * K + kh);
            cp16(bB + r * RSB + seg * 16, Bb + (size_t)r * K + kh);
        }
    };

    stage(0, 0);
    cp_commit();

    for (int kt = 0; kt < NT; kt++) {
        if (kt + 1 < NT) stage(kt + 1, (kt + 1) & 1);
        cp_commit();
        cp_wait1();
        __syncthreads();

        const uint32_t aS = sbase + (kt & 1) * STAGE_BH;
        const uint32_t bS = aS + TILE_BH;

        #pragma unroll
        for (int s = 0; s < 4; s++) {
            const int kb = s * 32;
            uint32_t afr[2][4];
            #pragma unroll
            for (int mt = 0; mt < 2; mt++)
                ldm_x4(afr[mt], aS + (wm0 + mt * 16 + a_r) * RSB + kb + a_k);
            uint32_t bfr[8][2];
            #pragma unroll
            for (int jj = 0; jj < 4; jj++) {
                uint32_t r[4];
                ldm_x4(r, bS + (wn0 + jj * 16 + b_r) * RSB + kb + b_k);
                bfr[jj * 2 + 0][0] = r[0]; bfr[jj * 2 + 0][1] = r[1];
                bfr[jj * 2 + 1][0] = r[2]; bfr[jj * 2 + 1][1] = r[3];
            }
            #pragma unroll
            for (int mt = 0; mt < 2; mt++)
                #pragma unroll
                for (int j = 0; j < 8; j++)
                    mma_f16(acc[mt][j], afr[mt], bfr[j]);
        }
        __syncthreads();
    }

    #pragma unroll
    for (int mt = 0; mt < 2; mt++) {
        #pragma unroll
        for (int e2 = 0; e2 < 2; e2++) {
            int mloc = wm0 + mt * 16 + grp + e2 * 8;
            if (c_sel == 1) {
                #pragma unroll
                for (int j = 0; j < 8; j++) {
                    half2 hv = __floats2half2_rn(acc[mt][j][e2 * 2 + 0],
                                                 acc[mt][j][e2 * 2 + 1]);
                    *(half2*)(Ch + (size_t)mloc * NPIX + wn0 + j * 8 + 2 * qid) = hv;
                }
            } else {
                float bv = bias[m0 + mloc];
                #pragma unroll
                for (int j = 0; j < 8; j++) {
                    float2 r;
                    r.x = acc[mt][j][e2 * 2 + 0] + bv;
                    r.y = acc[mt][j][e2 * 2 + 1] + bv;
                    *(float2*)(Cf + (size_t)mloc * NPIX + wn0 + j * 8 + 2 * qid) = r;
                }
            }
        }
    }
}

// ---------------------------------------------------------------------------
// 3x3 windowed attention — v-resident smem, 4-deep k ring, 1 sync/iteration.
// Block = 8row x 32col slab of one (b,h); warp w stages d-plane (dc+w).
// k: 4-buffer ring (one __syncthreads per iteration suffices: the staging
//    target buffer was last read two syncs ago). v: staged ONCE into a
//    persistent 8-chunk region during pass 1, in the same commit groups.
//    Pass 2 then runs barrier-free from smem.
// Tile row = 36 halves; j = gx+2; j=1/j=34 are the always-zero x-halo
// (pre-zeroed once; staging never writes them). Row-OOB via cp.async zfill.
// Zero-pad semantics: OOB logit contribution exactly 0.
// ---------------------------------------------------------------------------
#define DCH 8
#define TRR 10
#define TCH 36
#define PLANE_H (TRR * TCH)              // 360 halves per d-plane
#define CHUNK_H (DCH * PLANE_H)          // 2880 halves per chunk (5760 B)
#define KBUFS 4
#define ATT_SMEM ((KBUFS + 8) * CHUNK_H * 2)   // 69120 B

__global__ void __launch_bounds__(256)
attn_kernel(float* __restrict__ attn_out)
{
    __half* tk = (__half*)g_dsmem;           // [4][8][10][36]  k ring
    __half* tv = tk + KBUFS * CHUNK_H;       // [8][8][10][36]  v resident

    const int tid  = threadIdx.x;
    const int lane = tid & 31;
    const int warp = tid >> 5;
    const int ry   = warp;
    const int x    = lane;
    const int r0   = blockIdx.x * 8;
    const int h    = blockIdx.y;
    const int b    = blockIdx.z;
    const int p    = (r0 + ry) * 32 + x;

    const __half* __restrict__ qb = g_qkvh + ((size_t)b * MQKV +        h * DH) * NPIX;
    const __half* __restrict__ kb = g_qkvh + ((size_t)b * MQKV +  512 + h * DH) * NPIX;
    const __half* __restrict__ vb = g_qkvh + ((size_t)b * MQKV + 1024 + h * DH) * NPIX;

    // Pre-zero always-zero x-halo cols (j=1, j=34) across all 12 chunk regions.
    for (int r = tid; r < (KBUFS + 8) * DCH * TRR; r += 256) {
        tk[r * TCH + 1]  = __float2half(0.f);
        tk[r * TCH + 34] = __float2half(0.f);
    }

    // warp stages plane (dc + warp) into dstbuf: 10 rows x 16 aligned pairs
    auto stage = [&](const __half* __restrict__ src_base, int dc, __half* dstbuf) {
        const __half* __restrict__ src = src_base + (size_t)(dc + warp) * NPIX;
        const uint32_t dst =
            (uint32_t)__cvta_generic_to_shared(dstbuf + warp * PLANE_H);
        #pragma unroll
        for (int i0 = 0; i0 < 5; i0++) {
            const int i  = lane + i0 * 32;      // 0..159
            const int rr = i >> 4;
            const int t  = i & 15;              // pair gx = 2t,2t+1 -> j = 2t+2
            const int gy = r0 + rr - 1;
            cp4z(dst + (uint32_t)((rr * TCH + 2 * t + 2) * 2),
                 src + gy * 32 + 2 * t, ((unsigned)gy < 32u));
        }
    };

    // ---------------- Pass 1: dots = q . k  (v staged alongside) ----------
    float dots[9];
    #pragma unroll
    for (int w = 0; w < 9; w++) dots[w] = 0.f;

    // prologue: groups 0,1 (k + v for chunks 0,1)
    stage(kb, 0,   tk);             stage(vb, 0,   tv);             cp_commit();
    stage(kb, DCH, tk + CHUNK_H);   stage(vb, DCH, tv + CHUNK_H);   cp_commit();

    #pragma unroll 1
    for (int c = 0; c < DH / DCH; c++) {
        if (c + 2 < DH / DCH) {
            stage(kb, (c + 2) * DCH, tk + ((c + 2) & 3) * CHUNK_H);
            stage(vb, (c + 2) * DCH, tv + (c + 2) * CHUNK_H);
        }
        cp_commit();                 // group c+2 (possibly empty)
        cp_wait2();                  // group c complete (own copies)
        __syncthreads();             // all threads waited -> group c visible

        const __half* tkb = tk + (c & 3) * CHUNK_H;
        const int dc = c * DCH;
        float qv[DCH];
        #pragma unroll
        for (int dd = 0; dd < DCH; dd++)
            qv[dd] = __half2float(qb[(size_t)(dc + dd) * NPIX + p]);
        #pragma unroll
        for (int dd = 0; dd < DCH; dd++)
            #pragma unroll
            for (int w = 0; w < 9; w++)
                dots[w] += qv[dd] *
                    __half2float(tkb[dd * PLANE_H + (ry + w / 3) * TCH + x + 1 + w % 3]);
    }
    // After iter c=7: wait_group 2 covered groups <=7 (k AND v all complete),
    // followed by a full __syncthreads -> v region visible to all. Pass 2 is
    // read-only on smem: no further barriers needed.

    // softmax over 9 (OOB logits exactly 0)
    const float scale = 0.125f;
    float mx = -1e30f;
    #pragma unroll
    for (int w = 0; w < 9; w++) { dots[w] *= scale; mx = fmaxf(mx, dots[w]); }
    float a[9], sum = 0.f;
    #pragma unroll
    for (int w = 0; w < 9; w++) { a[w] = expf(dots[w] - mx); sum += a[w]; }
    float inv = 1.f / sum;
    #pragma unroll
    for (int w = 0; w < 9; w++) a[w] *= inv;

    {
        float* ao = attn_out + ((size_t)(b * HEADS + h) * NPIX + p) * 9;
        #pragma unroll
        for (int w = 0; w < 9; w++) ao[w] = a[w];
    }

    // ---------------- Pass 2: ctx = attn . v  (barrier-free) --------------
    __half* __restrict__ ct = g_ctxh + ((size_t)b * NPIX + p) * INNER + h * DH;

    #pragma unroll 2
    for (int c = 0; c < DH / DCH; c++) {
        const __half* tvb = tv + c * CHUNK_H;
        half2 hout[4];
        #pragma unroll
        for (int d2 = 0; d2 < 4; d2++) {
            float s0 = 0.f, s1 = 0.f;
            #pragma unroll
            for (int w = 0; w < 9; w++) {
                const int off = (ry + w / 3) * TCH + x + 1 + w % 3;
                s0 += a[w] * __half2float(tvb[(2 * d2 + 0) * PLANE_H + off]);
                s1 += a[w] * __half2float(tvb[(2 * d2 + 1) * PLANE_H + off]);
            }
            hout[d2] = __floats2half2_rn(s0, s1);
        }
        *(uint4*)(ct + c * DCH) = *(uint4*)hout;   // 16B aligned
    }
}

// ---------------------------------------------------------------------------
extern "C" void kernel_launch(void* const* d_in, const int* in_sizes, int n_in,
                              void* d_out, int out_size)
{
    const float* x   = (const float*)d_in[0];
    const float* Wq  = (const float*)d_in[1];
    const float* Wkv = (const float*)d_in[2];
    const float* Wo  = (const float*)d_in[3];
    const float* bo  = (const float*)d_in[4];
    float* out = (float*)d_out;     // out (4194304) | attn (1179648)

    static int smem_set = 0;
    if (!smem_set) {
        cudaFuncSetAttribute(gemm_h, cudaFuncAttributeMaxDynamicSharedMemorySize,
                             SMEM_GH);
        cudaFuncSetAttribute(attn_kernel, cudaFuncAttributeMaxDynamicSharedMemorySize,
                             ATT_SMEM);
        smem_set = 1;
    }

    // prep: transpose+round x, round weights (fp16)
    {
        dim3 g(32, 8, BATCH);
        prep_x<<<g, 256>>>(x);
        prep_w<<<512, 256>>>(Wq, Wkv, Wo);
    }

    // QKV: g_qkvh[b][m][p] = g_wh[m][:] . g_xh[b][p][:]   (K=256, NT=4)
    {
        dim3 grid(NPIX / 128, MQKV / 128, BATCH);   // (8, 12, 16)
        gemm_h<<<grid, 256, SMEM_GH>>>(1, 1, nullptr, 1, nullptr, MQKV, CIN);
    }

    // attention -> attn tail + g_ctxh
    {
        dim3 grid(4, HEADS, BATCH);                 // 512 blocks
        attn_kernel<<<grid, 256, ATT_SMEM>>>(out + OUT_ELEMS);
    }

    // out projection: out[b][c][p] = g_woh[c][:] . g_ctxh[b][p][:] + bo[c]  (K=512, NT=8)
    {
        dim3 grid(NPIX / 128, CIN / 128, BATCH);    // (8, 2, 16)
        gemm_h<<<grid, 256, SMEM_GH>>>(2, 2, out, 0, bo, CIN, INNER);
    }
}

// round 15
// speedup vs baseline: 1.9229x; 1.1154x over previous
#include <cuda_runtime.h>
#include <cuda_fp16.h>
#include <cstddef>
#include <cstdint>

#define BATCH   16
#define CIN     256
#define NPIX    1024
#define HEADS   8
#define DH      64
#define INNER   512
#define MQKV    1536
#define OUT_ELEMS   (BATCH * CIN * NPIX)            // 4194304

// Scratch (device globals: allocation-free rule) — fp16 intermediates
__device__ __half g_qkvT[(size_t)BATCH * NPIX * MQKV];   // [b][p][1536] q|k|v (d-contig)
__device__ __half g_xh  [(size_t)BATCH * NPIX * CIN ];   // [b][p][c]
__device__ __half g_ctxh[(size_t)BATCH * NPIX * INNER];  // [b][p][hd]
__device__ __half g_wh  [(size_t)MQKV * CIN ];           // [1536][256] (Wq|Wkv)
__device__ __half g_woh [(size_t)CIN  * INNER];          // [256][512]

// ---------------------------------------------------------------------------
// cp.async helpers
// ---------------------------------------------------------------------------
__device__ __forceinline__ void cp16(uint32_t dst, const void* src) {
    asm volatile("cp.async.cg.shared.global [%0], [%1], 16;" :: "r"(dst), "l"(src));
}
__device__ __forceinline__ void cp16z(uint32_t dst, const void* src, bool ok) {
    int sz = ok ? 16 : 0;
    asm volatile("cp.async.cg.shared.global [%0], [%1], 16, %2;"
                 :: "r"(dst), "l"(src), "r"(sz));
}
__device__ __forceinline__ void cp_commit() {
    asm volatile("cp.async.commit_group;" ::: "memory");
}
__device__ __forceinline__ void cp_wait1() {
    asm volatile("cp.async.wait_group 1;" ::: "memory");
}
__device__ __forceinline__ void cp_wait2() {
    asm volatile("cp.async.wait_group 2;" ::: "memory");
}
__device__ __forceinline__ void ldm_x4(uint32_t r[4], uint32_t saddr) {
    asm volatile("ldmatrix.sync.aligned.m8n8.x4.shared.b16 {%0,%1,%2,%3}, [%4];"
        : "=r"(r[0]), "=r"(r[1]), "=r"(r[2]), "=r"(r[3]) : "r"(saddr));
}
__device__ __forceinline__ void mma_f16(float c[4], const uint32_t a[4], const uint32_t b[2]) {
    asm volatile(
        "mma.sync.aligned.m16n8k16.row.col.f32.f16.f16.f32 "
        "{%0,%1,%2,%3},{%4,%5,%6,%7},{%8,%9},{%0,%1,%2,%3};"
        : "+f"(c[0]), "+f"(c[1]), "+f"(c[2]), "+f"(c[3])
        : "r"(a[0]), "r"(a[1]), "r"(a[2]), "r"(a[3]), "r"(b[0]), "r"(b[1]));
}

// ---------------------------------------------------------------------------
// Prep 1: transpose + fp16-round x: [b][c][p] -> g_xh[b][p][c]
// ---------------------------------------------------------------------------
__global__ void __launch_bounds__(256)
prep_x(const float* __restrict__ x)
{
    __shared__ float sm[32][33];
    const int b = blockIdx.z, ct = blockIdx.y, pt = blockIdx.x;
    const int t = threadIdx.x;
    const float* xb = x + ((size_t)b * CIN + ct * 32) * NPIX + pt * 32;
    const int cl = t >> 5, pl = t & 31;
    #pragma unroll
    for (int i = 0; i < 4; i++)
        sm[cl + i * 8][pl] = xb[(size_t)(cl + i * 8) * NPIX + pl];
    __syncthreads();
    __half* xo = g_xh + ((size_t)b * NPIX + pt * 32) * CIN + ct * 32;
    const int pr = t >> 5, cc = t & 31;
    #pragma unroll
    for (int i = 0; i < 4; i++)
        xo[(size_t)(pr + i * 8) * CIN + cc] = __float2half_rn(sm[cc][pr + i * 8]);
}

// ---------------------------------------------------------------------------
// Prep 2: fp16-round weights into g_wh (Wq|Wkv) and g_woh.
// ---------------------------------------------------------------------------
__global__ void __launch_bounds__(256)
prep_w(const float* __restrict__ Wq, const float* __restrict__ Wkv,
       const float* __restrict__ Wo)
{
    const int i = blockIdx.x * 256 + threadIdx.x;   // float4 index, grid covers 131072
    float4 v; __half* dst;
    if (i < 32768)      { v = ((const float4*)Wq)[i];          dst = g_wh  + (size_t)i * 4; }
    else if (i < 98304) { v = ((const float4*)Wkv)[i - 32768]; dst = g_wh  + (size_t)i * 4; }
    else                { v = ((const float4*)Wo)[i - 98304];  dst = g_woh + (size_t)(i - 98304) * 4; }
    *(half2*)(dst)     = __floats2half2_rn(v.x, v.y);
    *(half2*)(dst + 2) = __floats2half2_rn(v.z, v.w);
}

// ---------------------------------------------------------------------------
// Pipelined FP16 tensor-core GEMM (mma.m16n8k16, f32 accum).
// C = A[m][k] . B[z][p][k].  c_sel==1: transposed half store to g_qkvT[b][p][m]
// via smem bounce.  c_sel==0: float store + bias to Cext[z][m][p].
// ---------------------------------------------------------------------------
#define BKH 64
#define RSB 144
#define TILE_BH (128 * RSB)
#define STAGE_BH (2 * TILE_BH)
#define SMEM_GH (2 * STAGE_BH)       // 73728 B

extern __shared__ uint8_t g_dsmem[];

__global__ void __launch_bounds__(256, 2)
gemm_h(int a_sel, int b_sel, float* __restrict__ Cext, int c_sel,
       const float* __restrict__ bias, int M, int K)
{
    const int n0 = blockIdx.x * 128;
    const int m0 = blockIdx.y * 128;
    const int z  = blockIdx.z;

    const __half* __restrict__ A  = (a_sel == 1) ? g_wh : g_woh;
    const __half* __restrict__ Bm = (b_sel == 1) ? g_xh : g_ctxh;

    const __half* __restrict__ Ab = A + (size_t)m0 * K;
    const __half* __restrict__ Bb = Bm + ((size_t)z * NPIX + n0) * K;

    float* Cf = Cext + (size_t)z * CIN * NPIX + (size_t)m0 * NPIX + n0;

    const uint32_t sbase = (uint32_t)__cvta_generic_to_shared(g_dsmem);

    const int tid  = threadIdx.x;
    const int lane = tid & 31;
    const int warp = tid >> 5;
    const int wm0  = (warp >> 1) * 32;
    const int wn0  = (warp & 1) * 64;
    const int grp  = lane >> 2;
    const int qid  = lane & 3;

    const int sr  = tid >> 3;
    const int seg = tid & 7;

    const int a_r = ((lane >> 3) & 1) * 8 + (lane & 7);
    const int a_k = ((lane >> 4) & 1) * 16;
    const int b_r = ((lane >> 4) & 1) * 8 + (lane & 7);
    const int b_k = ((lane >> 3) & 1) * 16;

    float acc[2][8][4];
    #pragma unroll
    for (int mt = 0; mt < 2; mt++)
        #pragma unroll
        for (int j = 0; j < 8; j++)
            #pragma unroll
            for (int e = 0; e < 4; e++) acc[mt][j][e] = 0.f;

    const int NT = K / BKH;

    auto stage = [&](int kt, int s) {
        const uint32_t aB = sbase + s * STAGE_BH;
        const uint32_t bB = aB + TILE_BH;
        const int kh = kt * BKH + seg * 8;
        #pragma unroll
        for (int it = 0; it < 4; it++) {
            int r = sr + it * 32;
            cp16(aB + r * RSB + seg * 16, Ab + (size_t)r * K + kh);
            cp16(bB + r * RSB + seg * 16, Bb + (size_t)r * K + kh);
        }
    };

    stage(0, 0);
    cp_commit();

    for (int kt = 0; kt < NT; kt++) {
        if (kt + 1 < NT) stage(kt + 1, (kt + 1) & 1);
        cp_commit();
        cp_wait1();
        __syncthreads();

        const uint32_t aS = sbase + (kt & 1) * STAGE_BH;
        const uint32_t bS = aS + TILE_BH;

        #pragma unroll
        for (int s = 0; s < 4; s++) {
            const int kb = s * 32;
            uint32_t afr[2][4];
            #pragma unroll
            for (int mt = 0; mt < 2; mt++)
                ldm_x4(afr[mt], aS + (wm0 + mt * 16 + a_r) * RSB + kb + a_k);
            uint32_t bfr[8][2];
            #pragma unroll
            for (int jj = 0; jj < 4; jj++) {
                uint32_t r[4];
                ldm_x4(r, bS + (wn0 + jj * 16 + b_r) * RSB + kb + b_k);
                bfr[jj * 2 + 0][0] = r[0]; bfr[jj * 2 + 0][1] = r[1];
                bfr[jj * 2 + 1][0] = r[2]; bfr[jj * 2 + 1][1] = r[3];
            }
            #pragma unroll
            for (int mt = 0; mt < 2; mt++)
                #pragma unroll
                for (int j = 0; j < 8; j++)
                    mma_f16(acc[mt][j], afr[mt], bfr[j]);
        }
        __syncthreads();
    }

    if (c_sel == 1) {
        // Transposed epilogue: smem bounce [n=128][m=136 halves], then
        // coalesced 16B stores: 128 rows x 16 uint4-segments = 2048 uint4.
        __half* To = (__half*)g_dsmem;     // [128][136]
        #pragma unroll
        for (int mt = 0; mt < 2; mt++)
            #pragma unroll
            for (int e2 = 0; e2 < 2; e2++) {
                int m = wm0 + mt * 16 + grp + e2 * 8;
                #pragma unroll
                for (int j = 0; j < 8; j++) {
                    int n = wn0 + j * 8 + 2 * qid;
                    To[(n + 0) * 136 + m] = __float2half_rn(acc[mt][j][e2 * 2 + 0]);
                    To[(n + 1) * 136 + m] = __float2half_rn(acc[mt][j][e2 * 2 + 1]);
                }
            }
        __syncthreads();
        __half* base = g_qkvT + ((size_t)z * NPIX + n0) * MQKV + m0;
        #pragma unroll
        for (int i = 0; i < 8; i++) {
            int idx = tid + i * 256;        // 0..2047
            int n  = idx >> 4;              // 0..127
            int sg = idx & 15;              // 0..15 (16 x 8 halves = 128 m)
            uint4 val = *(uint4*)(To + n * 136 + sg * 8);
            *(uint4*)(base + (size_t)n * MQKV + sg * 8) = val;
        }
    } else {
        #pragma unroll
        for (int mt = 0; mt < 2; mt++)
            #pragma unroll
            for (int e2 = 0; e2 < 2; e2++) {
                int mloc = wm0 + mt * 16 + grp + e2 * 8;
                float bv = bias[m0 + mloc];
                #pragma unroll
                for (int j = 0; j < 8; j++) {
                    float2 r;
                    r.x = acc[mt][j][e2 * 2 + 0] + bv;
                    r.y = acc[mt][j][e2 * 2 + 1] + bv;
                    *(float2*)(Cf + (size_t)mloc * NPIX + wn0 + j * 8 + 2 * qid) = r;
                }
            }
    }
}

// ---------------------------------------------------------------------------
// 3x3 windowed attention — d-contiguous tiles, LDS.128 per window position.
// Block = 8row x 32col slab of one (b,h). Tile = [10 rows][34 cols][8 d] uint4
// per chunk; staged 16B/position via cp.async zfill (halo/OOB -> 0 == exact
// zero-pad: OOB logit contribution 0). k: 4-deep ring, 1 sync/iter. v: staged
// once during pass 1 (resident), pass 2 barrier-free.
// ---------------------------------------------------------------------------
#define TPOS 340                          // 10*34 positions per chunk
#define KBUFS 4
#define ATT_SMEM ((KBUFS + 8) * TPOS * 16)   // 65280 B

__global__ void __launch_bounds__(256)
attn_kernel(float* __restrict__ attn_out)
{
    uint4* tk4 = (uint4*)g_dsmem;          // [4][340]  k ring
    uint4* tv4 = tk4 + KBUFS * TPOS;       // [8][340]  v resident

    const int tid  = threadIdx.x;
    const int lane = tid & 31;
    const int warp = tid >> 5;
    const int ry   = warp;                 // row within slab
    const int x    = lane;                 // col
    const int r0   = blockIdx.x * 8;
    const int h    = blockIdx.y;
    const int b    = blockIdx.z;
    const int p    = (r0 + ry) * 32 + x;

    const __half* __restrict__ qT = g_qkvT + ((size_t)(b * NPIX + p)) * MQKV + h * DH;
    const __half* __restrict__ kBase = g_qkvT + (size_t)b * NPIX * MQKV + 512 + h * DH;
    const __half* __restrict__ vBase = kBase + 512;

    const int bidx = ry * 34 + x;          // this thread's tile position

    // stage one chunk (dc..dc+7) of src (k or v) into dstbuf (uint4[340])
    auto stageChunk = [&](const __half* __restrict__ src, int dc, uint4* dstbuf) {
        const uint32_t dsb = (uint32_t)__cvta_generic_to_shared(dstbuf);
        #pragma unroll
        for (int rep = 0; rep < 2; rep++) {
            const int rr = warp + rep * 8;
            if (rep == 0 || warp < 2) {
                const int gy = r0 + rr - 1;
                const bool rok = ((unsigned)gy < 32u);
                {
                    const int gx = lane - 1;
                    const bool ok = rok && ((unsigned)gx < 32u);
                    const __half* s = src + (ok ? (size_t)(gy * 32 + gx) * MQKV : 0) + dc;
                    cp16z(dsb + (uint32_t)((rr * 34 + lane) * 16), s, ok);
                }
                if (lane < 2) {
                    const int gx = lane + 31;
                    const bool ok = rok && ((unsigned)gx < 32u);
                    const __half* s = src + (ok ? (size_t)(gy * 32 + gx) * MQKV : 0) + dc;
                    cp16z(dsb + (uint32_t)((rr * 34 + lane + 32) * 16), s, ok);
                }
            }
        }
    };

    // window offsets in uint4 units
    const int WOFF[9] = {0, 1, 2, 34, 35, 36, 68, 69, 70};

    // ---------------- Pass 1: dots = q . k  (v staged alongside) ----------
    float dots[9];
    #pragma unroll
    for (int w = 0; w < 9; w++) dots[w] = 0.f;

    stageChunk(kBase, 0, tk4);          stageChunk(vBase, 0, tv4);          cp_commit();
    stageChunk(kBase, 8, tk4 + TPOS);   stageChunk(vBase, 8, tv4 + TPOS);   cp_commit();

    #pragma unroll 1
    for (int c = 0; c < 8; c++) {
        if (c + 2 < 8) {
            stageChunk(kBase, (c + 2) * 8, tk4 + ((c + 2) & 3) * TPOS);
            stageChunk(vBase, (c + 2) * 8, tv4 + (c + 2) * TPOS);
        }
        cp_commit();
        cp_wait2();
        __syncthreads();

        const uint4* kB = tk4 + (c & 3) * TPOS;
        uint4 q4 = *(const uint4*)(qT + c * 8);
        half2 qh[4];
        *(uint4*)qh = q4;
        #pragma unroll
        for (int w = 0; w < 9; w++) {
            uint4 kv = kB[bidx + WOFF[w]];
            half2 kh[4];
            *(uint4*)kh = kv;
            half2 s = __hmul2(qh[0], kh[0]);
            s = __hfma2(qh[1], kh[1], s);
            s = __hfma2(qh[2], kh[2], s);
            s = __hfma2(qh[3], kh[3], s);
            float2 f = __half22float2(s);
            dots[w] += f.x + f.y;
        }
    }
    // groups <=7 complete (k AND v), followed by __syncthreads -> v visible.

    // softmax over 9 (OOB logits exactly 0)
    const float scale = 0.125f;
    float mx = -1e30f;
    #pragma unroll
    for (int w = 0; w < 9; w++) { dots[w] *= scale; mx = fmaxf(mx, dots[w]); }
    float a[9], sum = 0.f;
    #pragma unroll
    for (int w = 0; w < 9; w++) { a[w] = expf(dots[w] - mx); sum += a[w]; }
    float inv = 1.f / sum;
    #pragma unroll
    for (int w = 0; w < 9; w++) a[w] *= inv;

    {
        float* ao = attn_out + ((size_t)(b * HEADS + h) * NPIX + p) * 9;
        #pragma unroll
        for (int w = 0; w < 9; w++) ao[w] = a[w];
    }

    // ---------------- Pass 2: ctx = attn . v  (barrier-free, float) -------
    __half* __restrict__ ct = g_ctxh + ((size_t)b * NPIX + p) * INNER + h * DH;

    #pragma unroll 1
    for (int c = 0; c < 8; c++) {
        const uint4* vB = tv4 + c * TPOS;
        float acc8[8];
        #pragma unroll
        for (int d = 0; d < 8; d++) acc8[d] = 0.f;
        #pragma unroll
        for (int w = 0; w < 9; w++) {
            uint4 vv = vB[bidx + WOFF[w]];
            half2 vh[4];
            *(uint4*)vh = vv;
            #pragma unroll
            for (int j = 0; j < 4; j++) {
                float2 f = __half22float2(vh[j]);
                acc8[2 * j + 0] += a[w] * f.x;
                acc8[2 * j + 1] += a[w] * f.y;
            }
        }
        half2 hout[4];
        #pragma unroll
        for (int j = 0; j < 4; j++)
            hout[j] = __floats2half2_rn(acc8[2 * j], acc8[2 * j + 1]);
        *(uint4*)(ct + c * 8) = *(uint4*)hout;
    }
}

// ---------------------------------------------------------------------------
extern "C" void kernel_launch(void* const* d_in, const int* in_sizes, int n_in,
                              void* d_out, int out_size)
{
    const float* x   = (const float*)d_in[0];
    const float* Wq  = (const float*)d_in[1];
    const float* Wkv = (const float*)d_in[2];
    const float* Wo  = (const float*)d_in[3];
    const float* bo  = (const float*)d_in[4];
    float* out = (float*)d_out;     // out (4194304) | attn (1179648)

    static int smem_set = 0;
    if (!smem_set) {
        cudaFuncSetAttribute(gemm_h, cudaFuncAttributeMaxDynamicSharedMemorySize,
                             SMEM_GH);
        cudaFuncSetAttribute(attn_kernel, cudaFuncAttributeMaxDynamicSharedMemorySize,
                             ATT_SMEM);
        smem_set = 1;
    }

    // prep: transpose+round x, round weights (fp16)
    {
        dim3 g(32, 8, BATCH);
        prep_x<<<g, 256>>>(x);
        prep_w<<<512, 256>>>(Wq, Wkv, Wo);
    }

    // QKV: g_qkvT[b][p][m] = g_wh[m][:] . g_xh[b][p][:]   (K=256, NT=4)
    {
        dim3 grid(NPIX / 128, MQKV / 128, BATCH);   // (8, 12, 16)
        gemm_h<<<grid, 256, SMEM_GH>>>(1, 1, nullptr, 1, nullptr, MQKV, CIN);
    }

    // attention -> attn tail + g_ctxh
    {
        dim3 grid(4, HEADS, BATCH);                 // 512 blocks
        attn_kernel<<<grid, 256, ATT_SMEM>>>(out + OUT_ELEMS);
    }

    // out projection: out[b][c][p] = g_woh[c][:] . g_ctxh[b][p][:] + bo[c]  (K=512, NT=8)
    {
        dim3 grid(NPIX / 128, CIN / 128, BATCH);    // (8, 2, 16)
        gemm_h<<<grid, 256, SMEM_GH>>>(2, 2, out, 0, bo, CIN, INNER);
    }
}